// round 1
// baseline (speedup 1.0000x reference)
#include <cuda_runtime.h>
#include <math.h>

#define N_AG 262144
#define GRID_SZ 1024
#define NCELL (GRID_SZ*GRID_SZ)
#define NCH 8
#define HID 64
#define DT 0.1f
#define DECAY 0.99f
#define SENSOR_ANGLE 0.6f
#define SENSOR_LEN 3.0f

// Scratch (allocation-free rule: __device__ globals)
__device__ int   g_claim[NCELL];                 // 4 MB : winning agent id per cell
__device__ float g_latT[(size_t)NCELL * NCH];    // 32 MB: channel-interleaved lattice copy
__device__ float g_dp[(size_t)N_AG * NCH];       // 8 MB : per-agent pheromone deposit

// Pass 0: reset claim, emit decayed lattice to output, build interleaved copy.
__global__ __launch_bounds__(256) void prep_kernel(const float* __restrict__ lat,
                                                   float* __restrict__ out_lat) {
    int idx = blockIdx.x * 256 + threadIdx.x;   // cell id = x*1024+y, grid covers NCELL
    g_claim[idx] = -1;
    float v[NCH];
#pragma unroll
    for (int c = 0; c < NCH; c++) {
        float t = lat[(c << 20) | idx];         // coalesced per-plane read
        v[c] = t;
        out_lat[(c << 20) | idx] = t * DECAY;   // coalesced write
    }
    float4* dst = reinterpret_cast<float4*>(&g_latT[(size_t)idx * NCH]);
    dst[0] = make_float4(v[0], v[1], v[2], v[3]);   // coalesced 32B/thread
    dst[1] = make_float4(v[4], v[5], v[6], v[7]);
}

// Pass 1: sense + MLP + pos/vel update + claim + stash deposit.
__global__ __launch_bounds__(256) void agent_kernel(
    const float* __restrict__ pos, const float* __restrict__ vel,
    const float* __restrict__ W1, const float* __restrict__ b1,
    const float* __restrict__ W2, const float* __restrict__ b2,
    float* __restrict__ out) {
    __shared__ float sW1[24 * HID];
    __shared__ float sW2[HID * 10];
    __shared__ float sb1[HID];
    __shared__ float sb2[10];
    int t = threadIdx.x;
    for (int i = t; i < 24 * HID; i += 256) sW1[i] = W1[i];
    for (int i = t; i < HID * 10; i += 256) sW2[i] = W2[i];
    if (t < HID) sb1[t] = b1[t];
    if (t < 10) sb2[t] = b2[t];
    __syncthreads();

    int i = blockIdx.x * 256 + t;
    float px = pos[i], py = pos[N_AG + i];
    float vx = vel[i], vy = vel[N_AG + i];
    float theta = atan2f(vy, vx);

    // ---- sense: 3 sensors x 3x3 cells, 8 channels each (one 32B group) ----
    float xa[24];
#pragma unroll
    for (int s = 0; s < 3; s++) {
        float off = (s == 0) ? 0.0f : ((s == 1) ? SENSOR_ANGLE : -SENSOR_ANGLE);
        float sn, cs;
        sincosf(theta + off, &sn, &cs);
        int cx = (int)rintf(px + SENSOR_LEN * cs);
        int cy = (int)rintf(py + SENSOR_LEN * sn);
        float4 a0 = make_float4(0.f, 0.f, 0.f, 0.f);
        float4 a1 = make_float4(0.f, 0.f, 0.f, 0.f);
#pragma unroll
        for (int dx = -1; dx <= 1; dx++) {
            int xi = (cx + dx) & (GRID_SZ - 1);
#pragma unroll
            for (int dy = -1; dy <= 1; dy++) {
                int yi = (cy + dy) & (GRID_SZ - 1);
                const float4* p = reinterpret_cast<const float4*>(
                    &g_latT[(size_t)((xi << 10) | yi) * NCH]);
                float4 l0 = p[0], l1 = p[1];
                a0.x += l0.x; a0.y += l0.y; a0.z += l0.z; a0.w += l0.w;
                a1.x += l1.x; a1.y += l1.y; a1.z += l1.z; a1.w += l1.w;
            }
        }
        xa[s * 8 + 0] = a0.x; xa[s * 8 + 1] = a0.y; xa[s * 8 + 2] = a0.z; xa[s * 8 + 3] = a0.w;
        xa[s * 8 + 4] = a1.x; xa[s * 8 + 5] = a1.y; xa[s * 8 + 6] = a1.z; xa[s * 8 + 7] = a1.w;
    }

    // ---- MLP: h_j streamed, never materialized as array ----
    float o[10];
#pragma unroll
    for (int k = 0; k < 10; k++) o[k] = sb2[k];
#pragma unroll 4
    for (int j = 0; j < HID; j++) {
        float a = sb1[j];
#pragma unroll
        for (int k = 0; k < 24; k++) a = fmaf(xa[k], sW1[k * HID + j], a);
        float hj = tanhf(a);
#pragma unroll
        for (int k = 0; k < 10; k++) o[k] = fmaf(hj, sW2[j * 10 + k], o[k]);
    }

    // ---- outputs ----
    float nvx = o[0], nvy = o[1];
    float npx = fmodf(px + nvx * DT, (float)GRID_SZ); if (npx < 0.f) npx += (float)GRID_SZ;
    float npy = fmodf(py + nvy * DT, (float)GRID_SZ); if (npy < 0.f) npy += (float)GRID_SZ;
    out[i]            = npx;
    out[N_AG + i]     = npy;
    out[2 * N_AG + i] = nvx;
    out[3 * N_AG + i] = nvy;

    float4* dpv = reinterpret_cast<float4*>(&g_dp[(size_t)i * NCH]);
    dpv[0] = make_float4(o[2], o[3], o[4], o[5]);
    dpv[1] = make_float4(o[6], o[7], o[8], o[9]);

    int xi = ((int)rintf(px)) & (GRID_SZ - 1);
    int yi = ((int)rintf(py)) & (GRID_SZ - 1);
    atomicMax(&g_claim[(xi << 10) | yi], i);    // last agent index wins (XLA scatter-set order)
}

// Pass 2: winner writes relu(cur + DT*dp) * DECAY into the output lattice.
__global__ __launch_bounds__(256) void deposit_kernel(const float* __restrict__ pos,
                                                      float* __restrict__ out_lat) {
    int i = blockIdx.x * 256 + threadIdx.x;
    float px = pos[i], py = pos[N_AG + i];
    int xi = ((int)rintf(px)) & (GRID_SZ - 1);
    int yi = ((int)rintf(py)) & (GRID_SZ - 1);
    int cell = (xi << 10) | yi;
    if (g_claim[cell] == i) {
        const float4* p = reinterpret_cast<const float4*>(&g_latT[(size_t)cell * NCH]);
        float4 l0 = p[0], l1 = p[1];
        const float4* dpv = reinterpret_cast<const float4*>(&g_dp[(size_t)i * NCH]);
        float4 d0 = dpv[0], d1 = dpv[1];
        out_lat[(0 << 20) | cell] = fmaxf(fmaf(DT, d0.x, l0.x), 0.f) * DECAY;
        out_lat[(1 << 20) | cell] = fmaxf(fmaf(DT, d0.y, l0.y), 0.f) * DECAY;
        out_lat[(2 << 20) | cell] = fmaxf(fmaf(DT, d0.z, l0.z), 0.f) * DECAY;
        out_lat[(3 << 20) | cell] = fmaxf(fmaf(DT, d0.w, l0.w), 0.f) * DECAY;
        out_lat[(4 << 20) | cell] = fmaxf(fmaf(DT, d1.x, l1.x), 0.f) * DECAY;
        out_lat[(5 << 20) | cell] = fmaxf(fmaf(DT, d1.y, l1.y), 0.f) * DECAY;
        out_lat[(6 << 20) | cell] = fmaxf(fmaf(DT, d1.z, l1.z), 0.f) * DECAY;
        out_lat[(7 << 20) | cell] = fmaxf(fmaf(DT, d1.w, l1.w), 0.f) * DECAY;
    }
}

extern "C" void kernel_launch(void* const* d_in, const int* in_sizes, int n_in,
                              void* d_out, int out_size) {
    const float* pos = (const float*)d_in[0];   // (2, N)
    const float* vel = (const float*)d_in[1];   // (2, N)
    const float* lat = (const float*)d_in[2];   // (8, 1024, 1024)
    const float* W1  = (const float*)d_in[3];   // (24, 64)
    const float* b1  = (const float*)d_in[4];   // (64,)
    const float* W2  = (const float*)d_in[5];   // (64, 10)
    const float* b2  = (const float*)d_in[6];   // (10,)
    float* out = (float*)d_out;
    float* out_lat = out + 4 * N_AG;

    prep_kernel<<<NCELL / 256, 256>>>(lat, out_lat);
    agent_kernel<<<N_AG / 256, 256>>>(pos, vel, W1, b1, W2, b2, out);
    deposit_kernel<<<N_AG / 256, 256>>>(pos, out_lat);
}

// round 2
// speedup vs baseline: 1.0999x; 1.0999x over previous
#include <cuda_runtime.h>
#include <math.h>

#define N_AG 262144
#define GRID_SZ 1024
#define NCELL (GRID_SZ*GRID_SZ)
#define NCH 8
#define HID 64
#define DT 0.1f
#define DECAY 0.99f
#define SENSOR_LEN 3.0f
// cos(0.6), sin(0.6)
#define COS_A 0.825335614909678f
#define SIN_A 0.564642473395035f

// Scratch (__device__ globals; no allocation allowed)
__device__ int   g_claim[NCELL];               // 4 MB : winning agent id per cell
__device__ float g_box[(size_t)NCELL * NCH];   // 32 MB: channel-interleaved 3x3 box sums
__device__ float g_dp[(size_t)N_AG * NCH];     // 8 MB : per-agent pheromone deposit

// Pass 0: reset claim, emit decayed lattice, build channel-interleaved 3x3 box-sum.
__global__ __launch_bounds__(256) void prep_kernel(const float* __restrict__ lat,
                                                   float* __restrict__ out_lat) {
    int idx = blockIdx.x * 256 + threadIdx.x;   // cell id = x*1024 + y
    g_claim[idx] = -1;
    int x  = idx >> 10, y = idx & 1023;
    int ym = (y + 1023) & 1023, yp = (y + 1) & 1023;
    int r0 = ((x + 1023) & 1023) << 10;  // x-1 row base
    int r1 = x << 10;                    // x   row base
    int r2 = ((x + 1) & 1023) << 10;     // x+1 row base

    float v[NCH];
#pragma unroll
    for (int c = 0; c < NCH; c++) {
        const float* L = lat + ((size_t)c << 20);
        float center = __ldg(&L[r1 | y]);
        float s = __ldg(&L[r0 | ym]) + __ldg(&L[r0 | y]) + __ldg(&L[r0 | yp])
                + __ldg(&L[r1 | ym]) + center            + __ldg(&L[r1 | yp])
                + __ldg(&L[r2 | ym]) + __ldg(&L[r2 | y]) + __ldg(&L[r2 | yp]);
        v[c] = s;
        out_lat[(c << 20) | idx] = center * DECAY;   // coalesced
    }
    float4* dst = reinterpret_cast<float4*>(&g_box[(size_t)idx * NCH]);
    dst[0] = make_float4(v[0], v[1], v[2], v[3]);
    dst[1] = make_float4(v[4], v[5], v[6], v[7]);
}

// Pass 1: sense (3 box reads) + MLP + pos/vel update + claim + stash deposit.
__global__ __launch_bounds__(256) void agent_kernel(
    const float* __restrict__ pos, const float* __restrict__ vel,
    const float* __restrict__ W1, const float* __restrict__ b1,
    const float* __restrict__ W2, const float* __restrict__ b2,
    float* __restrict__ out) {
    __shared__ float sW1T[HID * 24];   // transposed: [j][k], 96B rows (16B aligned)
    __shared__ float sW2p[HID * 12];   // padded:     [j][12], 48B rows (16B aligned)
    __shared__ float sb1[HID];
    __shared__ float sO0[12];
    int t = threadIdx.x;
    for (int i = t; i < HID * 24; i += 256) { int j = i / 24, k = i - j * 24; sW1T[i] = W1[k * HID + j]; }
    for (int i = t; i < HID * 12; i += 256) { int j = i / 12, k = i - j * 12; sW2p[i] = (k < 10) ? W2[j * 10 + k] : 0.f; }
    if (t < HID) sb1[t] = b1[t];
    if (t < 12)  sO0[t] = (t < 10) ? b2[t] : 0.f;
    __syncthreads();

    int i = blockIdx.x * 256 + t;
    float px = pos[i], py = pos[N_AG + i];
    float vx = vel[i], vy = vel[N_AG + i];

    // direction via normalization + angle-addition (no atan2/sincos)
    float invn = rsqrtf(fmaf(vx, vx, vy * vy));
    float c0 = vx * invn, s0 = vy * invn;
    float cs[3], sn[3];
    cs[0] = c0;                          sn[0] = s0;
    cs[1] = c0 * COS_A - s0 * SIN_A;     sn[1] = s0 * COS_A + c0 * SIN_A;  // +angle
    cs[2] = c0 * COS_A + s0 * SIN_A;     sn[2] = s0 * COS_A - c0 * SIN_A;  // -angle

    float xa[24];
#pragma unroll
    for (int s = 0; s < 3; s++) {
        int cx = (int)rintf(fmaf(SENSOR_LEN, cs[s], px));
        int cy = (int)rintf(fmaf(SENSOR_LEN, sn[s], py));
        int cell = ((cx & (GRID_SZ - 1)) << 10) | (cy & (GRID_SZ - 1));
        const float4* p = reinterpret_cast<const float4*>(&g_box[(size_t)cell * NCH]);
        float4 a0 = p[0], a1 = p[1];
        xa[s * 8 + 0] = a0.x; xa[s * 8 + 1] = a0.y; xa[s * 8 + 2] = a0.z; xa[s * 8 + 3] = a0.w;
        xa[s * 8 + 4] = a1.x; xa[s * 8 + 5] = a1.y; xa[s * 8 + 6] = a1.z; xa[s * 8 + 7] = a1.w;
    }

    // ---- MLP ----
    float o[12];
#pragma unroll
    for (int k = 0; k < 12; k++) o[k] = sO0[k];
#pragma unroll 4
    for (int j = 0; j < HID; j++) {
        const float4* w = reinterpret_cast<const float4*>(&sW1T[j * 24]);
        float a = sb1[j];
#pragma unroll
        for (int q = 0; q < 6; q++) {
            float4 wv = w[q];
            a = fmaf(xa[q * 4 + 0], wv.x, a);
            a = fmaf(xa[q * 4 + 1], wv.y, a);
            a = fmaf(xa[q * 4 + 2], wv.z, a);
            a = fmaf(xa[q * 4 + 3], wv.w, a);
        }
        float h;
        asm("tanh.approx.f32 %0, %1;" : "=f"(h) : "f"(a));
        const float4* w2 = reinterpret_cast<const float4*>(&sW2p[j * 12]);
#pragma unroll
        for (int q = 0; q < 3; q++) {
            float4 wv = w2[q];
            o[q * 4 + 0] = fmaf(h, wv.x, o[q * 4 + 0]);
            o[q * 4 + 1] = fmaf(h, wv.y, o[q * 4 + 1]);
            o[q * 4 + 2] = fmaf(h, wv.z, o[q * 4 + 2]);
            o[q * 4 + 3] = fmaf(h, wv.w, o[q * 4 + 3]);
        }
    }

    // ---- outputs ----
    float nvx = o[0], nvy = o[1];
    float npx = fmodf(fmaf(nvx, DT, px), (float)GRID_SZ); if (npx < 0.f) npx += (float)GRID_SZ;
    float npy = fmodf(fmaf(nvy, DT, py), (float)GRID_SZ); if (npy < 0.f) npy += (float)GRID_SZ;
    out[i]            = npx;
    out[N_AG + i]     = npy;
    out[2 * N_AG + i] = nvx;
    out[3 * N_AG + i] = nvy;

    float4* dpv = reinterpret_cast<float4*>(&g_dp[(size_t)i * NCH]);
    dpv[0] = make_float4(o[2], o[3], o[4], o[5]);
    dpv[1] = make_float4(o[6], o[7], o[8], o[9]);

    int xi = ((int)rintf(px)) & (GRID_SZ - 1);
    int yi = ((int)rintf(py)) & (GRID_SZ - 1);
    atomicMax(&g_claim[(xi << 10) | yi], i);    // last agent index wins (scatter-set order)
}

// Pass 2: winner writes relu(cur + DT*dp) * DECAY (cur from ORIGINAL lattice).
__global__ __launch_bounds__(256) void deposit_kernel(const float* __restrict__ pos,
                                                      const float* __restrict__ lat,
                                                      float* __restrict__ out_lat) {
    int i = blockIdx.x * 256 + threadIdx.x;
    float px = pos[i], py = pos[N_AG + i];
    int xi = ((int)rintf(px)) & (GRID_SZ - 1);
    int yi = ((int)rintf(py)) & (GRID_SZ - 1);
    int cell = (xi << 10) | yi;
    if (g_claim[cell] == i) {
        const float4* dpv = reinterpret_cast<const float4*>(&g_dp[(size_t)i * NCH]);
        float4 d0 = dpv[0], d1 = dpv[1];
        float dp[8] = {d0.x, d0.y, d0.z, d0.w, d1.x, d1.y, d1.z, d1.w};
#pragma unroll
        for (int c = 0; c < NCH; c++) {
            float cur = __ldg(&lat[(c << 20) | cell]);
            out_lat[(c << 20) | cell] = fmaxf(fmaf(DT, dp[c], cur), 0.f) * DECAY;
        }
    }
}

extern "C" void kernel_launch(void* const* d_in, const int* in_sizes, int n_in,
                              void* d_out, int out_size) {
    const float* pos = (const float*)d_in[0];   // (2, N)
    const float* vel = (const float*)d_in[1];   // (2, N)
    const float* lat = (const float*)d_in[2];   // (8, 1024, 1024)
    const float* W1  = (const float*)d_in[3];   // (24, 64)
    const float* b1  = (const float*)d_in[4];   // (64,)
    const float* W2  = (const float*)d_in[5];   // (64, 10)
    const float* b2  = (const float*)d_in[6];   // (10,)
    float* out = (float*)d_out;
    float* out_lat = out + 4 * N_AG;

    prep_kernel<<<NCELL / 256, 256>>>(lat, out_lat);
    agent_kernel<<<N_AG / 256, 256>>>(pos, vel, W1, b1, W2, b2, out);
    deposit_kernel<<<N_AG / 256, 256>>>(pos, lat, out_lat);
}

// round 3
// speedup vs baseline: 1.1185x; 1.0169x over previous
#include <cuda_runtime.h>
#include <math.h>

#define N_AG 262144
#define GRID_SZ 1024
#define NCELL (GRID_SZ*GRID_SZ)
#define NCH 8
#define HID 64
#define DT 0.1f
#define DECAY 0.99f
#define SENSOR_LEN 3.0f
// cos(0.6), sin(0.6)
#define COS_A 0.825335614909678f
#define SIN_A 0.564642473395035f

typedef unsigned long long ull;

// Scratch (__device__ globals; no allocation allowed)
__device__ int   g_claim[NCELL];               // 4 MB : winning agent id per cell
__device__ float g_box[(size_t)NCELL * NCH];   // 32 MB: channel-interleaved 3x3 box sums
__device__ float g_dp[(size_t)N_AG * NCH];     // 8 MB : per-agent pheromone deposit

__device__ __forceinline__ ull pk2(float lo, float hi) {
    ull r; asm("mov.b64 %0, {%1, %2};" : "=l"(r) : "f"(lo), "f"(hi)); return r;
}
__device__ __forceinline__ void upk2(ull v, float& lo, float& hi) {
    asm("mov.b64 {%0, %1}, %2;" : "=f"(lo), "=f"(hi) : "l"(v));
}
__device__ __forceinline__ ull fma2(ull a, ull b, ull c) {
    ull d; asm("fma.rn.f32x2 %0, %1, %2, %3;" : "=l"(d) : "l"(a), "l"(b), "l"(c)); return d;
}

// Pass 0: warp-per-128-cells. Column sums via 3 aligned coalesced loads,
// horizontal 3-tap via shfl (2 predicated edge lanes per warp per channel).
__global__ __launch_bounds__(256) void prep_kernel(const float* __restrict__ lat,
                                                   float* __restrict__ out_lat) {
    int x = blockIdx.x;                 // one lattice row per block
    int w = threadIdx.x >> 5, l = threadIdx.x & 31;
    int ybase = w << 7;                 // 8 warps * 128 y each
    int r0 = ((x + 1023) & 1023) << 10;
    int r1 = x << 10;
    int r2 = ((x + 1) & 1023) << 10;
    const unsigned FULL = 0xffffffffu;

#pragma unroll
    for (int i = 0; i < 4; i++) g_claim[r1 | (ybase + (i << 5) + l)] = -1;

    float v[NCH][4];
#pragma unroll
    for (int c = 0; c < NCH; c++) {
        const float* L = lat + ((size_t)c << 20);
        float* O = out_lat + ((size_t)c << 20);
        float cs[4];
#pragma unroll
        for (int i = 0; i < 4; i++) {
            int y = ybase + (i << 5) + l;
            float b = __ldg(&L[r1 | y]);
            cs[i] = __ldg(&L[r0 | y]) + b + __ldg(&L[r2 | y]);
            O[r1 | y] = b * DECAY;
        }
        float eL = 0.f, eR = 0.f;
        if (l == 0) {
            int yl = (ybase + 1023) & 1023;
            eL = __ldg(&L[r0 | yl]) + __ldg(&L[r1 | yl]) + __ldg(&L[r2 | yl]);
        }
        if (l == 31) {
            int yr = (ybase + 128) & 1023;
            eR = __ldg(&L[r0 | yr]) + __ldg(&L[r1 | yr]) + __ldg(&L[r2 | yr]);
        }
#pragma unroll
        for (int i = 0; i < 4; i++) {
            float left  = __shfl_up_sync(FULL, cs[i], 1);
            float right = __shfl_down_sync(FULL, cs[i], 1);
            float topPrev = (i > 0) ? __shfl_sync(FULL, cs[i - 1], 31) : eL;
            float botNext = (i < 3) ? __shfl_sync(FULL, cs[i + 1], 0)  : eR;
            if (l == 0)  left  = topPrev;
            if (l == 31) right = botNext;
            v[c][i] = left + cs[i] + right;
        }
    }
#pragma unroll
    for (int i = 0; i < 4; i++) {
        int cell = r1 | (ybase + (i << 5) + l);
        float4* dst = reinterpret_cast<float4*>(&g_box[(size_t)cell * NCH]);
        dst[0] = make_float4(v[0][i], v[1][i], v[2][i], v[3][i]);
        dst[1] = make_float4(v[4][i], v[5][i], v[6][i], v[7][i]);
    }
}

// Pass 1: sense (3 box reads) + packed-f32x2 MLP + updates + claim + deposit stash.
__global__ __launch_bounds__(256) void agent_kernel(
    const float* __restrict__ pos, const float* __restrict__ vel,
    const float* __restrict__ W1, const float* __restrict__ b1,
    const float* __restrict__ W2, const float* __restrict__ b2,
    float* __restrict__ out) {
    __shared__ float sW1[24 * HID];    // row-major [k][j]: LDS.128 -> two f32x2 pairs
    __shared__ float sW2p[HID * 12];   // padded [j][12], 48B rows, 16B aligned
    __shared__ float sb1[HID];
    __shared__ float sO0[12];
    int t = threadIdx.x;
    for (int i = t; i < 24 * HID; i += 256) sW1[i] = W1[i];
    for (int i = t; i < HID * 12; i += 256) { int j = i / 12, k = i - j * 12; sW2p[i] = (k < 10) ? W2[j * 10 + k] : 0.f; }
    if (t < HID) sb1[t] = b1[t];
    if (t < 12)  sO0[t] = (t < 10) ? b2[t] : 0.f;
    __syncthreads();

    int i = blockIdx.x * 256 + t;
    float px = pos[i], py = pos[N_AG + i];
    float vx = vel[i], vy = vel[N_AG + i];

    float invn = rsqrtf(fmaf(vx, vx, vy * vy));
    float c0 = vx * invn, s0 = vy * invn;
    float cs[3], sn[3];
    cs[0] = c0;                        sn[0] = s0;
    cs[1] = c0 * COS_A - s0 * SIN_A;   sn[1] = s0 * COS_A + c0 * SIN_A;  // +angle
    cs[2] = c0 * COS_A + s0 * SIN_A;   sn[2] = s0 * COS_A - c0 * SIN_A;  // -angle

    ull xa2[24];   // (xa_k, xa_k) duplicated pairs
#pragma unroll
    for (int s = 0; s < 3; s++) {
        int cx = (int)rintf(fmaf(SENSOR_LEN, cs[s], px));
        int cy = (int)rintf(fmaf(SENSOR_LEN, sn[s], py));
        int cell = ((cx & (GRID_SZ - 1)) << 10) | (cy & (GRID_SZ - 1));
        const float4* p = reinterpret_cast<const float4*>(&g_box[(size_t)cell * NCH]);
        float4 a0 = p[0], a1 = p[1];
        xa2[s * 8 + 0] = pk2(a0.x, a0.x); xa2[s * 8 + 1] = pk2(a0.y, a0.y);
        xa2[s * 8 + 2] = pk2(a0.z, a0.z); xa2[s * 8 + 3] = pk2(a0.w, a0.w);
        xa2[s * 8 + 4] = pk2(a1.x, a1.x); xa2[s * 8 + 5] = pk2(a1.y, a1.y);
        xa2[s * 8 + 6] = pk2(a1.z, a1.z); xa2[s * 8 + 7] = pk2(a1.w, a1.w);
    }

    // ---- MLP, 4 hidden units per iteration, packed f32x2 ----
    ull o2[6];
#pragma unroll
    for (int k = 0; k < 6; k++) o2[k] = pk2(sO0[2 * k], sO0[2 * k + 1]);

#pragma unroll 2
    for (int j = 0; j < HID; j += 4) {
        ulonglong2 bu = *reinterpret_cast<const ulonglong2*>(&sb1[j]);
        ull a01 = bu.x, a23 = bu.y;
#pragma unroll
        for (int k = 0; k < 24; k++) {
            ulonglong2 wu = *reinterpret_cast<const ulonglong2*>(&sW1[k * HID + j]);
            a01 = fma2(xa2[k], wu.x, a01);
            a23 = fma2(xa2[k], wu.y, a23);
        }
        float hv[4];
        upk2(a01, hv[0], hv[1]);
        upk2(a23, hv[2], hv[3]);
#pragma unroll
        for (int jj = 0; jj < 4; jj++) {
            float h;
            asm("tanh.approx.f32 %0, %1;" : "=f"(h) : "f"(hv[jj]));
            ull h2 = pk2(h, h);
            const ulonglong2* wp = reinterpret_cast<const ulonglong2*>(&sW2p[(j + jj) * 12]);
            ulonglong2 u0 = wp[0], u1 = wp[1], u2 = wp[2];
            o2[0] = fma2(h2, u0.x, o2[0]); o2[1] = fma2(h2, u0.y, o2[1]);
            o2[2] = fma2(h2, u1.x, o2[2]); o2[3] = fma2(h2, u1.y, o2[3]);
            o2[4] = fma2(h2, u2.x, o2[4]); o2[5] = fma2(h2, u2.y, o2[5]);
        }
    }
    float o[12];
#pragma unroll
    for (int k = 0; k < 6; k++) upk2(o2[k], o[2 * k], o[2 * k + 1]);

    // ---- outputs ----
    float nvx = o[0], nvy = o[1];
    float npx = fmaf(nvx, DT, px);
    float npy = fmaf(nvy, DT, py);
    if (npx >= (float)GRID_SZ) npx -= (float)GRID_SZ; else if (npx < 0.f) npx += (float)GRID_SZ;
    if (npy >= (float)GRID_SZ) npy -= (float)GRID_SZ; else if (npy < 0.f) npy += (float)GRID_SZ;
    out[i]            = npx;
    out[N_AG + i]     = npy;
    out[2 * N_AG + i] = nvx;
    out[3 * N_AG + i] = nvy;

    float4* dpv = reinterpret_cast<float4*>(&g_dp[(size_t)i * NCH]);
    dpv[0] = make_float4(o[2], o[3], o[4], o[5]);
    dpv[1] = make_float4(o[6], o[7], o[8], o[9]);

    int xi = ((int)rintf(px)) & (GRID_SZ - 1);
    int yi = ((int)rintf(py)) & (GRID_SZ - 1);
    atomicMax(&g_claim[(xi << 10) | yi], i);    // last agent index wins (scatter-set order)
}

// Pass 2: winner writes relu(cur + DT*dp) * DECAY (cur from ORIGINAL lattice).
__global__ __launch_bounds__(256) void deposit_kernel(const float* __restrict__ pos,
                                                      const float* __restrict__ lat,
                                                      float* __restrict__ out_lat) {
    int i = blockIdx.x * 256 + threadIdx.x;
    float px = pos[i], py = pos[N_AG + i];
    int xi = ((int)rintf(px)) & (GRID_SZ - 1);
    int yi = ((int)rintf(py)) & (GRID_SZ - 1);
    int cell = (xi << 10) | yi;
    if (g_claim[cell] == i) {
        const float4* dpv = reinterpret_cast<const float4*>(&g_dp[(size_t)i * NCH]);
        float4 d0 = dpv[0], d1 = dpv[1];
        float dp[8] = {d0.x, d0.y, d0.z, d0.w, d1.x, d1.y, d1.z, d1.w};
#pragma unroll
        for (int c = 0; c < NCH; c++) {
            float cur = __ldg(&lat[(c << 20) | cell]);
            out_lat[(c << 20) | cell] = fmaxf(fmaf(DT, dp[c], cur), 0.f) * DECAY;
        }
    }
}

extern "C" void kernel_launch(void* const* d_in, const int* in_sizes, int n_in,
                              void* d_out, int out_size) {
    const float* pos = (const float*)d_in[0];   // (2, N)
    const float* vel = (const float*)d_in[1];   // (2, N)
    const float* lat = (const float*)d_in[2];   // (8, 1024, 1024)
    const float* W1  = (const float*)d_in[3];   // (24, 64)
    const float* b1  = (const float*)d_in[4];   // (64,)
    const float* W2  = (const float*)d_in[5];   // (64, 10)
    const float* b2  = (const float*)d_in[6];   // (10,)
    float* out = (float*)d_out;
    float* out_lat = out + 4 * N_AG;

    prep_kernel<<<GRID_SZ, 256>>>(lat, out_lat);
    agent_kernel<<<N_AG / 256, 256>>>(pos, vel, W1, b1, W2, b2, out);
    deposit_kernel<<<N_AG / 256, 256>>>(pos, lat, out_lat);
}

// round 4
// speedup vs baseline: 1.2202x; 1.0909x over previous
#include <cuda_runtime.h>
#include <math.h>

#define N_AG 262144
#define GRID_SZ 1024
#define NCELL (GRID_SZ*GRID_SZ)
#define NCH 8
#define HID 64
#define DT 0.1f
#define DECAY 0.99f
#define SENSOR_LEN 3.0f
// cos(0.6), sin(0.6)
#define COS_A 0.825335614909678f
#define SIN_A 0.564642473395035f

typedef unsigned long long ull;

// Scratch (__device__ globals; no allocation allowed)
__device__ int   g_claim[NCELL];               // 4 MB : winning agent id per cell
__device__ float g_box[(size_t)NCELL * NCH];   // 32 MB: channel-interleaved 3x3 box sums
__device__ float g_dp[(size_t)N_AG * NCH];     // 8 MB : per-agent pheromone deposit

__device__ __forceinline__ ull pk2(float lo, float hi) {
    ull r; asm("mov.b64 %0, {%1, %2};" : "=l"(r) : "f"(lo), "f"(hi)); return r;
}
__device__ __forceinline__ void upk2(ull v, float& lo, float& hi) {
    asm("mov.b64 {%0, %1}, %2;" : "=f"(lo), "=f"(hi) : "l"(v));
}
__device__ __forceinline__ ull fma2(ull a, ull b, ull c) {
    ull d; asm("fma.rn.f32x2 %0, %1, %2, %3;" : "=l"(d) : "l"(a), "l"(b), "l"(c)); return d;
}

// Pass 0: thread owns 4 consecutive y-cells of one row. All-float4 loads,
// vertical vector add, horizontal 3-tap in registers. No shfl, no misalignment.
__global__ __launch_bounds__(256) void prep_kernel(const float* __restrict__ lat,
                                                   float* __restrict__ out_lat) {
    int tid = blockIdx.x * 256 + threadIdx.x;  // NCELL/4 threads
    int x  = tid >> 8;
    int y0 = (tid & 255) << 2;
    int r0 = ((x + 1023) & 1023) << 10;
    int r1 = x << 10;
    int r2 = ((x + 1) & 1023) << 10;
    int ym = (y0 + 1020) & 1023;   // y0-4 (aligned)
    int yp = (y0 + 4) & 1023;      // y0+4 (aligned)

    *reinterpret_cast<int4*>(&g_claim[r1 | y0]) = make_int4(-1, -1, -1, -1);

    float v[NCH][4];
#pragma unroll
    for (int c = 0; c < NCH; c++) {
        const float* L = lat + ((size_t)c << 20);
        float4 m0 = __ldg((const float4*)&L[r0 | ym]);
        float4 b0 = __ldg((const float4*)&L[r0 | y0]);
        float4 p0 = __ldg((const float4*)&L[r0 | yp]);
        float4 m1 = __ldg((const float4*)&L[r1 | ym]);
        float4 b1v = __ldg((const float4*)&L[r1 | y0]);
        float4 p1 = __ldg((const float4*)&L[r1 | yp]);
        float4 m2 = __ldg((const float4*)&L[r2 | ym]);
        float4 b2v = __ldg((const float4*)&L[r2 | y0]);
        float4 p2 = __ldg((const float4*)&L[r2 | yp]);

        float4 V = make_float4(b0.x + b1v.x + b2v.x, b0.y + b1v.y + b2v.y,
                               b0.z + b1v.z + b2v.z, b0.w + b1v.w + b2v.w);
        float VL = m0.w + m1.w + m2.w;
        float VR = p0.x + p1.x + p2.x;
        v[c][0] = VL  + V.x + V.y;
        v[c][1] = V.x + V.y + V.z;
        v[c][2] = V.y + V.z + V.w;
        v[c][3] = V.z + V.w + VR;

        float4* O = reinterpret_cast<float4*>(&out_lat[((size_t)c << 20) | (r1 | y0)]);
        *O = make_float4(b1v.x * DECAY, b1v.y * DECAY, b1v.z * DECAY, b1v.w * DECAY);
    }
#pragma unroll
    for (int i = 0; i < 4; i++) {
        int cell = r1 | (y0 + i);
        float4* dst = reinterpret_cast<float4*>(&g_box[(size_t)cell * NCH]);
        dst[0] = make_float4(v[0][i], v[1][i], v[2][i], v[3][i]);
        dst[1] = make_float4(v[4][i], v[5][i], v[6][i], v[7][i]);
    }
}

// sense one agent -> 24 duplicated f32x2 inputs
__device__ __forceinline__ void sense_agent(float px, float py, float vx, float vy,
                                            ull* xa2) {
    float invn = rsqrtf(fmaf(vx, vx, vy * vy));
    float c0 = vx * invn, s0 = vy * invn;
    float cs[3], sn[3];
    cs[0] = c0;                        sn[0] = s0;
    cs[1] = c0 * COS_A - s0 * SIN_A;   sn[1] = s0 * COS_A + c0 * SIN_A;
    cs[2] = c0 * COS_A + s0 * SIN_A;   sn[2] = s0 * COS_A - c0 * SIN_A;
#pragma unroll
    for (int s = 0; s < 3; s++) {
        int cx = (int)rintf(fmaf(SENSOR_LEN, cs[s], px));
        int cy = (int)rintf(fmaf(SENSOR_LEN, sn[s], py));
        int cell = ((cx & (GRID_SZ - 1)) << 10) | (cy & (GRID_SZ - 1));
        const float4* p = reinterpret_cast<const float4*>(&g_box[(size_t)cell * NCH]);
        float4 a0 = p[0], a1 = p[1];
        xa2[s * 8 + 0] = pk2(a0.x, a0.x); xa2[s * 8 + 1] = pk2(a0.y, a0.y);
        xa2[s * 8 + 2] = pk2(a0.z, a0.z); xa2[s * 8 + 3] = pk2(a0.w, a0.w);
        xa2[s * 8 + 4] = pk2(a1.x, a1.x); xa2[s * 8 + 5] = pk2(a1.y, a1.y);
        xa2[s * 8 + 6] = pk2(a1.z, a1.z); xa2[s * 8 + 7] = pk2(a1.w, a1.w);
    }
}

// Pass 1: two agents per thread -> each weight LDS.128 feeds 4 fma2.
__global__ __launch_bounds__(128) void agent_kernel(
    const float* __restrict__ pos, const float* __restrict__ vel,
    const float* __restrict__ W1, const float* __restrict__ b1,
    const float* __restrict__ W2, const float* __restrict__ b2,
    float* __restrict__ out) {
    __shared__ float sW1[24 * HID];    // row-major [k][j]
    __shared__ float sW2p[HID * 12];   // padded [j][12]
    __shared__ float sb1[HID];
    __shared__ float sO0[12];
    int t = threadIdx.x;
    for (int i = t; i < 24 * HID; i += 128) sW1[i] = W1[i];
    for (int i = t; i < HID * 12; i += 128) { int j = i / 12, k = i - j * 12; sW2p[i] = (k < 10) ? W2[j * 10 + k] : 0.f; }
    if (t < HID) sb1[t] = b1[t];
    if (t < 12)  sO0[t] = (t < 10) ? b2[t] : 0.f;
    __syncthreads();

    int g = blockIdx.x * 128 + t;           // handles agents 2g, 2g+1
    float2 pxv = ((const float2*)pos)[g];
    float2 pyv = ((const float2*)(pos + N_AG))[g];
    float2 vxv = ((const float2*)vel)[g];
    float2 vyv = ((const float2*)(vel + N_AG))[g];

    ull xaA[24], xaB[24];
    sense_agent(pxv.x, pyv.x, vxv.x, vyv.x, xaA);
    sense_agent(pxv.y, pyv.y, vxv.y, vyv.y, xaB);

    ull oA[6], oB[6];
#pragma unroll
    for (int k = 0; k < 6; k++) { ull z = pk2(sO0[2 * k], sO0[2 * k + 1]); oA[k] = z; oB[k] = z; }

#pragma unroll 1
    for (int j = 0; j < HID; j += 4) {
        ulonglong2 bu = *reinterpret_cast<const ulonglong2*>(&sb1[j]);
        ull aA01 = bu.x, aA23 = bu.y, aB01 = bu.x, aB23 = bu.y;
#pragma unroll
        for (int k = 0; k < 24; k++) {
            ulonglong2 wu = *reinterpret_cast<const ulonglong2*>(&sW1[k * HID + j]);
            aA01 = fma2(xaA[k], wu.x, aA01);
            aA23 = fma2(xaA[k], wu.y, aA23);
            aB01 = fma2(xaB[k], wu.x, aB01);
            aB23 = fma2(xaB[k], wu.y, aB23);
        }
        float hA[4], hB[4];
        upk2(aA01, hA[0], hA[1]); upk2(aA23, hA[2], hA[3]);
        upk2(aB01, hB[0], hB[1]); upk2(aB23, hB[2], hB[3]);
#pragma unroll
        for (int jj = 0; jj < 4; jj++) {
            float ha, hb;
            asm("tanh.approx.f32 %0, %1;" : "=f"(ha) : "f"(hA[jj]));
            asm("tanh.approx.f32 %0, %1;" : "=f"(hb) : "f"(hB[jj]));
            ull h2a = pk2(ha, ha), h2b = pk2(hb, hb);
            const ulonglong2* wp = reinterpret_cast<const ulonglong2*>(&sW2p[(j + jj) * 12]);
            ulonglong2 u0 = wp[0], u1 = wp[1], u2 = wp[2];
            oA[0] = fma2(h2a, u0.x, oA[0]); oA[1] = fma2(h2a, u0.y, oA[1]);
            oA[2] = fma2(h2a, u1.x, oA[2]); oA[3] = fma2(h2a, u1.y, oA[3]);
            oA[4] = fma2(h2a, u2.x, oA[4]); oA[5] = fma2(h2a, u2.y, oA[5]);
            oB[0] = fma2(h2b, u0.x, oB[0]); oB[1] = fma2(h2b, u0.y, oB[1]);
            oB[2] = fma2(h2b, u1.x, oB[2]); oB[3] = fma2(h2b, u1.y, oB[3]);
            oB[4] = fma2(h2b, u2.x, oB[4]); oB[5] = fma2(h2b, u2.y, oB[5]);
        }
    }
    float fA[12], fB[12];
#pragma unroll
    for (int k = 0; k < 6; k++) { upk2(oA[k], fA[2 * k], fA[2 * k + 1]); upk2(oB[k], fB[2 * k], fB[2 * k + 1]); }

    // ---- outputs ----
    float npxA = fmaf(fA[0], DT, pxv.x), npyA = fmaf(fA[1], DT, pyv.x);
    float npxB = fmaf(fB[0], DT, pxv.y), npyB = fmaf(fB[1], DT, pyv.y);
    if (npxA >= (float)GRID_SZ) npxA -= (float)GRID_SZ; else if (npxA < 0.f) npxA += (float)GRID_SZ;
    if (npyA >= (float)GRID_SZ) npyA -= (float)GRID_SZ; else if (npyA < 0.f) npyA += (float)GRID_SZ;
    if (npxB >= (float)GRID_SZ) npxB -= (float)GRID_SZ; else if (npxB < 0.f) npxB += (float)GRID_SZ;
    if (npyB >= (float)GRID_SZ) npyB -= (float)GRID_SZ; else if (npyB < 0.f) npyB += (float)GRID_SZ;

    ((float2*)out)[g]                     = make_float2(npxA, npxB);
    ((float2*)(out + N_AG))[g]            = make_float2(npyA, npyB);
    ((float2*)(out + 2 * N_AG))[g]        = make_float2(fA[0], fB[0]);
    ((float2*)(out + 3 * N_AG))[g]        = make_float2(fA[1], fB[1]);

    int a0 = 2 * g, a1 = 2 * g + 1;
    float4* dpv = reinterpret_cast<float4*>(&g_dp[(size_t)a0 * NCH]);
    dpv[0] = make_float4(fA[2], fA[3], fA[4], fA[5]);
    dpv[1] = make_float4(fA[6], fA[7], fA[8], fA[9]);
    dpv[2] = make_float4(fB[2], fB[3], fB[4], fB[5]);
    dpv[3] = make_float4(fB[6], fB[7], fB[8], fB[9]);

    int xiA = ((int)rintf(pxv.x)) & (GRID_SZ - 1);
    int yiA = ((int)rintf(pyv.x)) & (GRID_SZ - 1);
    atomicMax(&g_claim[(xiA << 10) | yiA], a0);
    int xiB = ((int)rintf(pxv.y)) & (GRID_SZ - 1);
    int yiB = ((int)rintf(pyv.y)) & (GRID_SZ - 1);
    atomicMax(&g_claim[(xiB << 10) | yiB], a1);
}

// Pass 2: winner writes relu(cur + DT*dp) * DECAY (cur from ORIGINAL lattice).
__global__ __launch_bounds__(256) void deposit_kernel(const float* __restrict__ pos,
                                                      const float* __restrict__ lat,
                                                      float* __restrict__ out_lat) {
    int i = blockIdx.x * 256 + threadIdx.x;
    float px = pos[i], py = pos[N_AG + i];
    int xi = ((int)rintf(px)) & (GRID_SZ - 1);
    int yi = ((int)rintf(py)) & (GRID_SZ - 1);
    int cell = (xi << 10) | yi;
    if (g_claim[cell] == i) {
        const float4* dpv = reinterpret_cast<const float4*>(&g_dp[(size_t)i * NCH]);
        float4 d0 = dpv[0], d1 = dpv[1];
        float dp[8] = {d0.x, d0.y, d0.z, d0.w, d1.x, d1.y, d1.z, d1.w};
#pragma unroll
        for (int c = 0; c < NCH; c++) {
            float cur = __ldg(&lat[(c << 20) | cell]);
            out_lat[(c << 20) | cell] = fmaxf(fmaf(DT, dp[c], cur), 0.f) * DECAY;
        }
    }
}

extern "C" void kernel_launch(void* const* d_in, const int* in_sizes, int n_in,
                              void* d_out, int out_size) {
    const float* pos = (const float*)d_in[0];   // (2, N)
    const float* vel = (const float*)d_in[1];   // (2, N)
    const float* lat = (const float*)d_in[2];   // (8, 1024, 1024)
    const float* W1  = (const float*)d_in[3];   // (24, 64)
    const float* b1  = (const float*)d_in[4];   // (64,)
    const float* W2  = (const float*)d_in[5];   // (64, 10)
    const float* b2  = (const float*)d_in[6];   // (10,)
    float* out = (float*)d_out;
    float* out_lat = out + 4 * N_AG;

    prep_kernel<<<NCELL / 4 / 256, 256>>>(lat, out_lat);
    agent_kernel<<<N_AG / 2 / 128, 128>>>(pos, vel, W1, b1, W2, b2, out);
    deposit_kernel<<<N_AG / 256, 256>>>(pos, lat, out_lat);
}

// round 5
// speedup vs baseline: 1.2428x; 1.0185x over previous
#include <cuda_runtime.h>
#include <math.h>

#define N_AG 262144
#define GRID_SZ 1024
#define NCELL (GRID_SZ*GRID_SZ)
#define NCH 8
#define HID 64
#define DT 0.1f
#define DECAY 0.99f
#define SENSOR_LEN 3.0f
// cos(0.6), sin(0.6)
#define COS_A 0.825335614909678f
#define SIN_A 0.564642473395035f

typedef unsigned long long ull;

// Scratch (__device__ globals; no allocation allowed)
__device__ int   g_claim[NCELL];               // 4 MB : winning agent id per cell
__device__ float g_box[(size_t)NCELL * NCH];   // 32 MB: channel-interleaved 3x3 box sums
__device__ float g_dp[(size_t)N_AG * NCH];     // 8 MB : per-agent pheromone deposit

__device__ __forceinline__ ull pk2(float lo, float hi) {
    ull r; asm("mov.b64 %0, {%1, %2};" : "=l"(r) : "f"(lo), "f"(hi)); return r;
}
__device__ __forceinline__ void upk2(ull v, float& lo, float& hi) {
    asm("mov.b64 {%0, %1}, %2;" : "=f"(lo), "=f"(hi) : "l"(v));
}
__device__ __forceinline__ ull fma2(ull a, ull b, ull c) {
    ull d; asm("fma.rn.f32x2 %0, %1, %2, %3;" : "=l"(d) : "l"(a), "l"(b), "l"(c)); return d;
}

// Pass 0: block = one lattice row. Column sums for all 8 channels staged in smem
// (each gmem float read once per block), horizontal 3-tap from smem. One sync.
__global__ __launch_bounds__(256) void prep_kernel(const float* __restrict__ lat,
                                                   float* __restrict__ out_lat) {
    __shared__ float cs_s[NCH][GRID_SZ];
    int x = blockIdx.x;
    int t = threadIdx.x;
    int y0 = t << 2;
    int r0 = ((x + 1023) & 1023) << 10;
    int r1 = x << 10;
    int r2 = ((x + 1) & 1023) << 10;

    *reinterpret_cast<int4*>(&g_claim[r1 | y0]) = make_int4(-1, -1, -1, -1);

#pragma unroll
    for (int c = 0; c < NCH; c++) {
        const float* L = lat + ((size_t)c << 20);
        float4 a = __ldg((const float4*)&L[r0 | y0]);
        float4 b = __ldg((const float4*)&L[r1 | y0]);
        float4 d = __ldg((const float4*)&L[r2 | y0]);
        *reinterpret_cast<float4*>(&cs_s[c][y0]) =
            make_float4(a.x + b.x + d.x, a.y + b.y + d.y,
                        a.z + b.z + d.z, a.w + b.w + d.w);
        *reinterpret_cast<float4*>(&out_lat[((size_t)c << 20) | (r1 | y0)]) =
            make_float4(b.x * DECAY, b.y * DECAY, b.z * DECAY, b.w * DECAY);
    }
    __syncthreads();

    float v[NCH][4];
    int yl = (y0 + 1023) & 1023;   // y0-1
    int yr = (y0 + 4) & 1023;      // y0+4
#pragma unroll
    for (int c = 0; c < NCH; c++) {
        float c0 = cs_s[c][y0], c1 = cs_s[c][y0 + 1];
        float c2 = cs_s[c][y0 + 2], c3 = cs_s[c][y0 + 3];
        float eL = cs_s[c][yl], eR = cs_s[c][yr];
        v[c][0] = eL + c0 + c1;
        v[c][1] = c0 + c1 + c2;
        v[c][2] = c1 + c2 + c3;
        v[c][3] = c2 + c3 + eR;
    }
#pragma unroll
    for (int i = 0; i < 4; i++) {
        int cell = r1 | (y0 + i);
        float4* dst = reinterpret_cast<float4*>(&g_box[(size_t)cell * NCH]);
        dst[0] = make_float4(v[0][i], v[1][i], v[2][i], v[3][i]);
        dst[1] = make_float4(v[4][i], v[5][i], v[6][i], v[7][i]);
    }
}

// sense one agent -> 24 plain floats (packed on the fly in the MLP loop)
__device__ __forceinline__ void sense_agent(float px, float py, float vx, float vy,
                                            float* xa) {
    float invn = rsqrtf(fmaf(vx, vx, vy * vy));
    float c0 = vx * invn, s0 = vy * invn;
    float cs[3], sn[3];
    cs[0] = c0;                        sn[0] = s0;
    cs[1] = c0 * COS_A - s0 * SIN_A;   sn[1] = s0 * COS_A + c0 * SIN_A;
    cs[2] = c0 * COS_A + s0 * SIN_A;   sn[2] = s0 * COS_A - c0 * SIN_A;
#pragma unroll
    for (int s = 0; s < 3; s++) {
        int cx = (int)rintf(fmaf(SENSOR_LEN, cs[s], px));
        int cy = (int)rintf(fmaf(SENSOR_LEN, sn[s], py));
        int cell = ((cx & (GRID_SZ - 1)) << 10) | (cy & (GRID_SZ - 1));
        const float4* p = reinterpret_cast<const float4*>(&g_box[(size_t)cell * NCH]);
        float4 a0 = p[0], a1 = p[1];
        xa[s * 8 + 0] = a0.x; xa[s * 8 + 1] = a0.y; xa[s * 8 + 2] = a0.z; xa[s * 8 + 3] = a0.w;
        xa[s * 8 + 4] = a1.x; xa[s * 8 + 5] = a1.y; xa[s * 8 + 6] = a1.z; xa[s * 8 + 7] = a1.w;
    }
}

// Pass 1: two agents per thread; weight LDS.128 feeds 4 fma2; on-the-fly input dup.
__global__ __launch_bounds__(128, 3) void agent_kernel(
    const float* __restrict__ pos, const float* __restrict__ vel,
    const float* __restrict__ W1, const float* __restrict__ b1,
    const float* __restrict__ W2, const float* __restrict__ b2,
    float* __restrict__ out) {
    __shared__ float sW1[24 * HID];    // row-major [k][j]
    __shared__ float sW2p[HID * 12];   // padded [j][12]
    __shared__ float sb1[HID];
    __shared__ float sO0[12];
    int t = threadIdx.x;
    for (int i = t; i < 24 * HID; i += 128) sW1[i] = W1[i];
    for (int i = t; i < HID * 12; i += 128) { int j = i / 12, k = i - j * 12; sW2p[i] = (k < 10) ? W2[j * 10 + k] : 0.f; }
    if (t < HID) sb1[t] = b1[t];
    if (t < 12)  sO0[t] = (t < 10) ? b2[t] : 0.f;
    __syncthreads();

    int g = blockIdx.x * 128 + t;           // handles agents 2g, 2g+1
    float2 pxv = ((const float2*)pos)[g];
    float2 pyv = ((const float2*)(pos + N_AG))[g];
    float2 vxv = ((const float2*)vel)[g];
    float2 vyv = ((const float2*)(vel + N_AG))[g];

    float xaA[24], xaB[24];
    sense_agent(pxv.x, pyv.x, vxv.x, vyv.x, xaA);
    sense_agent(pxv.y, pyv.y, vxv.y, vyv.y, xaB);

    ull oA[6], oB[6];
#pragma unroll
    for (int k = 0; k < 6; k++) { ull z = pk2(sO0[2 * k], sO0[2 * k + 1]); oA[k] = z; oB[k] = z; }

#pragma unroll 1
    for (int j = 0; j < HID; j += 4) {
        ulonglong2 bu = *reinterpret_cast<const ulonglong2*>(&sb1[j]);
        ull aA01 = bu.x, aA23 = bu.y, aB01 = bu.x, aB23 = bu.y;
#pragma unroll
        for (int k = 0; k < 24; k++) {
            ulonglong2 wu = *reinterpret_cast<const ulonglong2*>(&sW1[k * HID + j]);
            ull xA2 = pk2(xaA[k], xaA[k]);
            ull xB2 = pk2(xaB[k], xaB[k]);
            aA01 = fma2(xA2, wu.x, aA01);
            aA23 = fma2(xA2, wu.y, aA23);
            aB01 = fma2(xB2, wu.x, aB01);
            aB23 = fma2(xB2, wu.y, aB23);
        }
        float hA[4], hB[4];
        upk2(aA01, hA[0], hA[1]); upk2(aA23, hA[2], hA[3]);
        upk2(aB01, hB[0], hB[1]); upk2(aB23, hB[2], hB[3]);
#pragma unroll
        for (int jj = 0; jj < 4; jj++) {
            float ha, hb;
            asm("tanh.approx.f32 %0, %1;" : "=f"(ha) : "f"(hA[jj]));
            asm("tanh.approx.f32 %0, %1;" : "=f"(hb) : "f"(hB[jj]));
            ull h2a = pk2(ha, ha), h2b = pk2(hb, hb);
            const ulonglong2* wp = reinterpret_cast<const ulonglong2*>(&sW2p[(j + jj) * 12]);
            ulonglong2 u0 = wp[0], u1 = wp[1], u2 = wp[2];
            oA[0] = fma2(h2a, u0.x, oA[0]); oA[1] = fma2(h2a, u0.y, oA[1]);
            oA[2] = fma2(h2a, u1.x, oA[2]); oA[3] = fma2(h2a, u1.y, oA[3]);
            oA[4] = fma2(h2a, u2.x, oA[4]); oA[5] = fma2(h2a, u2.y, oA[5]);
            oB[0] = fma2(h2b, u0.x, oB[0]); oB[1] = fma2(h2b, u0.y, oB[1]);
            oB[2] = fma2(h2b, u1.x, oB[2]); oB[3] = fma2(h2b, u1.y, oB[3]);
            oB[4] = fma2(h2b, u2.x, oB[4]); oB[5] = fma2(h2b, u2.y, oB[5]);
        }
    }
    float fA[12], fB[12];
#pragma unroll
    for (int k = 0; k < 6; k++) { upk2(oA[k], fA[2 * k], fA[2 * k + 1]); upk2(oB[k], fB[2 * k], fB[2 * k + 1]); }

    // ---- outputs ----
    float npxA = fmaf(fA[0], DT, pxv.x), npyA = fmaf(fA[1], DT, pyv.x);
    float npxB = fmaf(fB[0], DT, pxv.y), npyB = fmaf(fB[1], DT, pyv.y);
    if (npxA >= (float)GRID_SZ) npxA -= (float)GRID_SZ; else if (npxA < 0.f) npxA += (float)GRID_SZ;
    if (npyA >= (float)GRID_SZ) npyA -= (float)GRID_SZ; else if (npyA < 0.f) npyA += (float)GRID_SZ;
    if (npxB >= (float)GRID_SZ) npxB -= (float)GRID_SZ; else if (npxB < 0.f) npxB += (float)GRID_SZ;
    if (npyB >= (float)GRID_SZ) npyB -= (float)GRID_SZ; else if (npyB < 0.f) npyB += (float)GRID_SZ;

    ((float2*)out)[g]              = make_float2(npxA, npxB);
    ((float2*)(out + N_AG))[g]     = make_float2(npyA, npyB);
    ((float2*)(out + 2 * N_AG))[g] = make_float2(fA[0], fB[0]);
    ((float2*)(out + 3 * N_AG))[g] = make_float2(fA[1], fB[1]);

    int a0 = 2 * g, a1 = 2 * g + 1;
    float4* dpv = reinterpret_cast<float4*>(&g_dp[(size_t)a0 * NCH]);
    dpv[0] = make_float4(fA[2], fA[3], fA[4], fA[5]);
    dpv[1] = make_float4(fA[6], fA[7], fA[8], fA[9]);
    dpv[2] = make_float4(fB[2], fB[3], fB[4], fB[5]);
    dpv[3] = make_float4(fB[6], fB[7], fB[8], fB[9]);

    int xiA = ((int)rintf(pxv.x)) & (GRID_SZ - 1);
    int yiA = ((int)rintf(pyv.x)) & (GRID_SZ - 1);
    atomicMax(&g_claim[(xiA << 10) | yiA], a0);
    int xiB = ((int)rintf(pxv.y)) & (GRID_SZ - 1);
    int yiB = ((int)rintf(pyv.y)) & (GRID_SZ - 1);
    atomicMax(&g_claim[(xiB << 10) | yiB], a1);
}

// Pass 2: winner writes relu(cur + DT*dp) * DECAY (cur from ORIGINAL lattice).
__global__ __launch_bounds__(256) void deposit_kernel(const float* __restrict__ pos,
                                                      const float* __restrict__ lat,
                                                      float* __restrict__ out_lat) {
    int i = blockIdx.x * 256 + threadIdx.x;
    float px = pos[i], py = pos[N_AG + i];
    int xi = ((int)rintf(px)) & (GRID_SZ - 1);
    int yi = ((int)rintf(py)) & (GRID_SZ - 1);
    int cell = (xi << 10) | yi;
    if (g_claim[cell] == i) {
        const float4* dpv = reinterpret_cast<const float4*>(&g_dp[(size_t)i * NCH]);
        float4 d0 = dpv[0], d1 = dpv[1];
        float dp[8] = {d0.x, d0.y, d0.z, d0.w, d1.x, d1.y, d1.z, d1.w};
#pragma unroll
        for (int c = 0; c < NCH; c++) {
            float cur = __ldg(&lat[(c << 20) | cell]);
            out_lat[(c << 20) | cell] = fmaxf(fmaf(DT, dp[c], cur), 0.f) * DECAY;
        }
    }
}

extern "C" void kernel_launch(void* const* d_in, const int* in_sizes, int n_in,
                              void* d_out, int out_size) {
    const float* pos = (const float*)d_in[0];   // (2, N)
    const float* vel = (const float*)d_in[1];   // (2, N)
    const float* lat = (const float*)d_in[2];   // (8, 1024, 1024)
    const float* W1  = (const float*)d_in[3];   // (24, 64)
    const float* b1  = (const float*)d_in[4];   // (64,)
    const float* W2  = (const float*)d_in[5];   // (64, 10)
    const float* b2  = (const float*)d_in[6];   // (10,)
    float* out = (float*)d_out;
    float* out_lat = out + 4 * N_AG;

    prep_kernel<<<GRID_SZ, 256>>>(lat, out_lat);
    agent_kernel<<<N_AG / 2 / 128, 128>>>(pos, vel, W1, b1, W2, b2, out);
    deposit_kernel<<<N_AG / 256, 256>>>(pos, lat, out_lat);
}

// round 6
// speedup vs baseline: 1.3575x; 1.0923x over previous
#include <cuda_runtime.h>
#include <math.h>

#define N_AG 262144
#define GRID_SZ 1024
#define NCELL (GRID_SZ*GRID_SZ)
#define NCH 8
#define HID 64
#define DT 0.1f
#define DECAY 0.99f
#define SENSOR_LEN 3.0f
// cos(0.6), sin(0.6)
#define COS_A 0.825335614909678f
#define SIN_A 0.564642473395035f

typedef unsigned long long ull;

// Scratch (__device__ globals; no allocation allowed)
__device__ int    g_claim[NCELL];        // 4 MB : winning agent id per cell
__device__ float4 g_boxA[NCELL];         // 16 MB: 3x3 box sums, channels 0-3
__device__ float4 g_boxB[NCELL];         // 16 MB: 3x3 box sums, channels 4-7
__device__ float  g_dp[(size_t)N_AG * NCH];  // 8 MB : per-agent deposit

__device__ __forceinline__ ull pk2(float lo, float hi) {
    ull r; asm("mov.b64 %0, {%1, %2};" : "=l"(r) : "f"(lo), "f"(hi)); return r;
}
__device__ __forceinline__ void upk2(ull v, float& lo, float& hi) {
    asm("mov.b64 {%0, %1}, %2;" : "=f"(lo), "=f"(hi) : "l"(v));
}
__device__ __forceinline__ ull fma2(ull a, ull b, ull c) {
    ull d; asm("fma.rn.f32x2 %0, %1, %2, %3;" : "=l"(d) : "l"(a), "l"(b), "l"(c)); return d;
}

// Pass 0: block = one lattice row. Phase A: coalesced float4 loads build
// column sums in smem + decayed output. Phase B: threads remapped to
// stride-256 cells so box-sum stores are perfectly coalesced (16B lane stride).
__global__ __launch_bounds__(256) void prep_kernel(const float* __restrict__ lat,
                                                   float* __restrict__ out_lat) {
    __shared__ float cs_s[NCH][GRID_SZ];
    int x = blockIdx.x;
    int t = threadIdx.x;
    int y0 = t << 2;
    int r0 = ((x + 1023) & 1023) << 10;
    int r1 = x << 10;
    int r2 = ((x + 1) & 1023) << 10;

    *reinterpret_cast<int4*>(&g_claim[r1 | y0]) = make_int4(-1, -1, -1, -1);

#pragma unroll
    for (int c = 0; c < NCH; c++) {
        const float* L = lat + ((size_t)c << 20);
        float4 a = __ldg((const float4*)&L[r0 | y0]);
        float4 b = __ldg((const float4*)&L[r1 | y0]);
        float4 d = __ldg((const float4*)&L[r2 | y0]);
        *reinterpret_cast<float4*>(&cs_s[c][y0]) =
            make_float4(a.x + b.x + d.x, a.y + b.y + d.y,
                        a.z + b.z + d.z, a.w + b.w + d.w);
        *reinterpret_cast<float4*>(&out_lat[((size_t)c << 20) | (r1 | y0)]) =
            make_float4(b.x * DECAY, b.y * DECAY, b.z * DECAY, b.w * DECAY);
    }
    __syncthreads();

#pragma unroll
    for (int i = 0; i < 4; i++) {
        int y  = t + (i << 8);               // stride-256 cell ownership
        int ym = (y + 1023) & 1023;
        int yp = (y + 1) & 1023;
        float v[NCH];
#pragma unroll
        for (int c = 0; c < NCH; c++)
            v[c] = cs_s[c][ym] + cs_s[c][y] + cs_s[c][yp];
        int cell = r1 | y;
        g_boxA[cell] = make_float4(v[0], v[1], v[2], v[3]);   // 16B lane stride
        g_boxB[cell] = make_float4(v[4], v[5], v[6], v[7]);
    }
}

// sense one agent -> 24 plain floats
__device__ __forceinline__ void sense_agent(float px, float py, float vx, float vy,
                                            float* xa) {
    float invn = rsqrtf(fmaf(vx, vx, vy * vy));
    float c0 = vx * invn, s0 = vy * invn;
    float cs[3], sn[3];
    cs[0] = c0;                        sn[0] = s0;
    cs[1] = c0 * COS_A - s0 * SIN_A;   sn[1] = s0 * COS_A + c0 * SIN_A;
    cs[2] = c0 * COS_A + s0 * SIN_A;   sn[2] = s0 * COS_A - c0 * SIN_A;
#pragma unroll
    for (int s = 0; s < 3; s++) {
        int cx = (int)rintf(fmaf(SENSOR_LEN, cs[s], px));
        int cy = (int)rintf(fmaf(SENSOR_LEN, sn[s], py));
        int cell = ((cx & (GRID_SZ - 1)) << 10) | (cy & (GRID_SZ - 1));
        float4 a0 = __ldg(&g_boxA[cell]);
        float4 a1 = __ldg(&g_boxB[cell]);
        xa[s * 8 + 0] = a0.x; xa[s * 8 + 1] = a0.y; xa[s * 8 + 2] = a0.z; xa[s * 8 + 3] = a0.w;
        xa[s * 8 + 4] = a1.x; xa[s * 8 + 5] = a1.y; xa[s * 8 + 6] = a1.z; xa[s * 8 + 7] = a1.w;
    }
}

// Pass 1: two agents per thread; weight LDS.128 broadcast feeds 4 fma2.
__global__ __launch_bounds__(128, 4) void agent_kernel(
    const float* __restrict__ pos, const float* __restrict__ vel,
    const float* __restrict__ W1, const float* __restrict__ b1,
    const float* __restrict__ W2, const float* __restrict__ b2,
    float* __restrict__ out) {
    __shared__ float sW1[24 * HID];    // row-major [k][j]
    __shared__ float sW2p[HID * 12];   // padded [j][12]
    __shared__ float sb1[HID];
    __shared__ float sO0[12];
    int t = threadIdx.x;
    for (int i = t; i < 24 * HID; i += 128) sW1[i] = W1[i];
    for (int i = t; i < HID * 12; i += 128) { int j = i / 12, k = i - j * 12; sW2p[i] = (k < 10) ? W2[j * 10 + k] : 0.f; }
    if (t < HID) sb1[t] = b1[t];
    if (t < 12)  sO0[t] = (t < 10) ? b2[t] : 0.f;
    __syncthreads();

    int g = blockIdx.x * 128 + t;           // handles agents 2g, 2g+1
    float2 pxv = ((const float2*)pos)[g];
    float2 pyv = ((const float2*)(pos + N_AG))[g];
    float2 vxv = ((const float2*)vel)[g];
    float2 vyv = ((const float2*)(vel + N_AG))[g];

    float xaA[24], xaB[24];
    sense_agent(pxv.x, pyv.x, vxv.x, vyv.x, xaA);
    sense_agent(pxv.y, pyv.y, vxv.y, vyv.y, xaB);

    ull oA[6], oB[6];
#pragma unroll
    for (int k = 0; k < 6; k++) { ull z = pk2(sO0[2 * k], sO0[2 * k + 1]); oA[k] = z; oB[k] = z; }

#pragma unroll 1
    for (int j = 0; j < HID; j += 4) {
        ulonglong2 bu = *reinterpret_cast<const ulonglong2*>(&sb1[j]);
        ull aA01 = bu.x, aA23 = bu.y, aB01 = bu.x, aB23 = bu.y;
#pragma unroll
        for (int k = 0; k < 24; k++) {
            ulonglong2 wu = *reinterpret_cast<const ulonglong2*>(&sW1[k * HID + j]);
            ull xA2 = pk2(xaA[k], xaA[k]);
            ull xB2 = pk2(xaB[k], xaB[k]);
            aA01 = fma2(xA2, wu.x, aA01);
            aA23 = fma2(xA2, wu.y, aA23);
            aB01 = fma2(xB2, wu.x, aB01);
            aB23 = fma2(xB2, wu.y, aB23);
        }
        float hA[4], hB[4];
        upk2(aA01, hA[0], hA[1]); upk2(aA23, hA[2], hA[3]);
        upk2(aB01, hB[0], hB[1]); upk2(aB23, hB[2], hB[3]);
#pragma unroll
        for (int jj = 0; jj < 4; jj++) {
            float ha, hb;
            asm("tanh.approx.f32 %0, %1;" : "=f"(ha) : "f"(hA[jj]));
            asm("tanh.approx.f32 %0, %1;" : "=f"(hb) : "f"(hB[jj]));
            ull h2a = pk2(ha, ha), h2b = pk2(hb, hb);
            const ulonglong2* wp = reinterpret_cast<const ulonglong2*>(&sW2p[(j + jj) * 12]);
            ulonglong2 u0 = wp[0], u1 = wp[1], u2 = wp[2];
            oA[0] = fma2(h2a, u0.x, oA[0]); oA[1] = fma2(h2a, u0.y, oA[1]);
            oA[2] = fma2(h2a, u1.x, oA[2]); oA[3] = fma2(h2a, u1.y, oA[3]);
            oA[4] = fma2(h2a, u2.x, oA[4]); oA[5] = fma2(h2a, u2.y, oA[5]);
            oB[0] = fma2(h2b, u0.x, oB[0]); oB[1] = fma2(h2b, u0.y, oB[1]);
            oB[2] = fma2(h2b, u1.x, oB[2]); oB[3] = fma2(h2b, u1.y, oB[3]);
            oB[4] = fma2(h2b, u2.x, oB[4]); oB[5] = fma2(h2b, u2.y, oB[5]);
        }
    }
    float fA[12], fB[12];
#pragma unroll
    for (int k = 0; k < 6; k++) { upk2(oA[k], fA[2 * k], fA[2 * k + 1]); upk2(oB[k], fB[2 * k], fB[2 * k + 1]); }

    // ---- outputs ----
    float npxA = fmaf(fA[0], DT, pxv.x), npyA = fmaf(fA[1], DT, pyv.x);
    float npxB = fmaf(fB[0], DT, pxv.y), npyB = fmaf(fB[1], DT, pyv.y);
    if (npxA >= (float)GRID_SZ) npxA -= (float)GRID_SZ; else if (npxA < 0.f) npxA += (float)GRID_SZ;
    if (npyA >= (float)GRID_SZ) npyA -= (float)GRID_SZ; else if (npyA < 0.f) npyA += (float)GRID_SZ;
    if (npxB >= (float)GRID_SZ) npxB -= (float)GRID_SZ; else if (npxB < 0.f) npxB += (float)GRID_SZ;
    if (npyB >= (float)GRID_SZ) npyB -= (float)GRID_SZ; else if (npyB < 0.f) npyB += (float)GRID_SZ;

    ((float2*)out)[g]              = make_float2(npxA, npxB);
    ((float2*)(out + N_AG))[g]     = make_float2(npyA, npyB);
    ((float2*)(out + 2 * N_AG))[g] = make_float2(fA[0], fB[0]);
    ((float2*)(out + 3 * N_AG))[g] = make_float2(fA[1], fB[1]);

    int a0 = 2 * g, a1 = 2 * g + 1;
    float4* dpv = reinterpret_cast<float4*>(&g_dp[(size_t)a0 * NCH]);
    dpv[0] = make_float4(fA[2], fA[3], fA[4], fA[5]);
    dpv[1] = make_float4(fA[6], fA[7], fA[8], fA[9]);
    dpv[2] = make_float4(fB[2], fB[3], fB[4], fB[5]);
    dpv[3] = make_float4(fB[6], fB[7], fB[8], fB[9]);

    int xiA = ((int)rintf(pxv.x)) & (GRID_SZ - 1);
    int yiA = ((int)rintf(pyv.x)) & (GRID_SZ - 1);
    atomicMax(&g_claim[(xiA << 10) | yiA], a0);
    int xiB = ((int)rintf(pxv.y)) & (GRID_SZ - 1);
    int yiB = ((int)rintf(pyv.y)) & (GRID_SZ - 1);
    atomicMax(&g_claim[(xiB << 10) | yiB], a1);
}

// Pass 2: winner writes relu(cur + DT*dp) * DECAY (cur from ORIGINAL lattice).
__global__ __launch_bounds__(256) void deposit_kernel(const float* __restrict__ pos,
                                                      const float* __restrict__ lat,
                                                      float* __restrict__ out_lat) {
    int i = blockIdx.x * 256 + threadIdx.x;
    float px = pos[i], py = pos[N_AG + i];
    int xi = ((int)rintf(px)) & (GRID_SZ - 1);
    int yi = ((int)rintf(py)) & (GRID_SZ - 1);
    int cell = (xi << 10) | yi;
    if (g_claim[cell] == i) {
        const float4* dpv = reinterpret_cast<const float4*>(&g_dp[(size_t)i * NCH]);
        float4 d0 = dpv[0], d1 = dpv[1];
        float dp[8] = {d0.x, d0.y, d0.z, d0.w, d1.x, d1.y, d1.z, d1.w};
#pragma unroll
        for (int c = 0; c < NCH; c++) {
            float cur = __ldg(&lat[(c << 20) | cell]);
            out_lat[(c << 20) | cell] = fmaxf(fmaf(DT, dp[c], cur), 0.f) * DECAY;
        }
    }
}

extern "C" void kernel_launch(void* const* d_in, const int* in_sizes, int n_in,
                              void* d_out, int out_size) {
    const float* pos = (const float*)d_in[0];   // (2, N)
    const float* vel = (const float*)d_in[1];   // (2, N)
    const float* lat = (const float*)d_in[2];   // (8, 1024, 1024)
    const float* W1  = (const float*)d_in[3];   // (24, 64)
    const float* b1  = (const float*)d_in[4];   // (64,)
    const float* W2  = (const float*)d_in[5];   // (64, 10)
    const float* b2  = (const float*)d_in[6];   // (10,)
    float* out = (float*)d_out;
    float* out_lat = out + 4 * N_AG;

    prep_kernel<<<GRID_SZ, 256>>>(lat, out_lat);
    agent_kernel<<<N_AG / 2 / 128, 128>>>(pos, vel, W1, b1, W2, b2, out);
    deposit_kernel<<<N_AG / 256, 256>>>(pos, lat, out_lat);
}